// round 14
// baseline (speedup 1.0000x reference)
#include <cuda_runtime.h>
#include <cuda_fp16.h>
#include <cstdint>

#define B_ 32
#define S_ 1024
#define D_ 512
#define SCALE 0.044194173824159216f   // 1/sqrt(512)

// Fallback scratch in case out_size does not include the attn_sm output.
__device__ float g_attn_scratch[(size_t)B_ * S_ * S_];

// pack two f32 -> f16x2 (lo = first element), round-to-nearest
__device__ __forceinline__ uint32_t f2h2(float lo, float hi) {
    uint32_t r;
    asm("cvt.rn.f16x2.f32 %0, %1, %2;" : "=r"(r) : "f"(hi), "f"(lo));
    return r;
}

__device__ __forceinline__ void mma_f16(float* c, const uint32_t* a, const uint32_t* b) {
    asm volatile(
        "mma.sync.aligned.m16n8k16.row.col.f32.f16.f16.f32 "
        "{%0,%1,%2,%3}, {%4,%5,%6,%7}, {%8,%9}, {%0,%1,%2,%3};\n"
        : "+f"(c[0]), "+f"(c[1]), "+f"(c[2]), "+f"(c[3])
        : "r"(a[0]), "r"(a[1]), "r"(a[2]), "r"(a[3]),
          "r"(b[0]), "r"(b[1]));
}
__device__ __forceinline__ void ldsm4(uint32_t& r0, uint32_t& r1, uint32_t& r2, uint32_t& r3, uint32_t a) {
    asm volatile("ldmatrix.sync.aligned.m8n8.x4.shared.b16 {%0,%1,%2,%3}, [%4];"
                 : "=r"(r0), "=r"(r1), "=r"(r2), "=r"(r3) : "r"(a));
}
__device__ __forceinline__ void ldsm4t(uint32_t& r0, uint32_t& r1, uint32_t& r2, uint32_t& r3, uint32_t a) {
    asm volatile("ldmatrix.sync.aligned.m8n8.x4.trans.shared.b16 {%0,%1,%2,%3}, [%4];"
                 : "=r"(r0), "=r"(r1), "=r"(r2), "=r"(r3) : "r"(a));
}

// ---------------------------------------------------------------------------
// Kernel 1: masked_vec = (Q K^T)*SCALE*mask.  128x128 tile, BK=64 (f32 cols),
// fp16 m16n8k16, 3-stage smem ring, producer LDG f32 -> cvt f16x2 -> STS.
// Consumer: fragment-pipelined (B double-buffered per k16, A one step ahead).
// ---------------------------------------------------------------------------
__global__ __launch_bounds__(256, 2) void qk_kernel(
    const float* __restrict__ Q, const float* __restrict__ K,
    const int* __restrict__ rep, float* __restrict__ attn_param)
{
    float* attn = attn_param ? attn_param : g_attn_scratch;
    const int bm = blockIdx.y, bn = blockIdx.x, b = blockIdx.z;
    const int m0 = bm * 128, n0 = bn * 128;
    const int tid = threadIdx.x;
    float* attn_b = attn + (size_t)b * S_ * S_;

    if (bn > bm) {
        float4 z = make_float4(0.f, 0.f, 0.f, 0.f);
        #pragma unroll
        for (int i = 0; i < 16; i++) {
            int idx = tid + i * 256;
            int r = idx >> 5, c = idx & 31;
            reinterpret_cast<float4*>(attn_b + (size_t)(m0 + r) * S_ + n0)[c] = z;
        }
        return;
    }

    extern __shared__ float smem[];              // 3 stages x 32KB (A16K + B16K)
    const uint32_t smem_u = (uint32_t)__cvta_generic_to_shared(smem);

    const int warp = tid >> 5, lane = tid & 31;
    const int wm = warp & 1, wn = warp >> 1;
    const int gID = lane >> 2, tig = lane & 3;

    const float* Qb = Q + ((size_t)b * S_ + m0) * D_;
    const float* Kb = K + ((size_t)b * S_ + n0) * D_;

    // producer: 8 threads per row (32B f32 each), rows lr+32i, chunk = lc
    const int lr = tid >> 3, lc = tid & 7;
    const uint32_t psw = (uint32_t)((lc ^ (lr & 7)) << 4);

    const int l7 = lane & 7;
    const int lb1 = (lane >> 3) & 1;
    const int lb2 = lane >> 4;                   // 0/1
    const int nb8 = lb2 * 8;                     // +8 rows for ldsm4-B hi pair

    float acc[4][4][4];
    #pragma unroll
    for (int i = 0; i < 4; i++)
        #pragma unroll
        for (int j = 0; j < 4; j++)
            #pragma unroll
            for (int r = 0; r < 4; r++) acc[i][j][r] = 0.f;

    uint4 qh[4], kh[4];

    #define QK_LDG(kk) do {                                                    \
        _Pragma("unroll")                                                      \
        for (int i_ = 0; i_ < 4; i_++) {                                       \
            int r_ = lr + i_ * 32;                                             \
            const float* pq = Qb + (size_t)r_ * D_ + (kk) + lc * 8;            \
            float4 x = *reinterpret_cast<const float4*>(pq);                   \
            float4 y = *reinterpret_cast<const float4*>(pq + 4);               \
            qh[i_].x = f2h2(x.x, x.y); qh[i_].y = f2h2(x.z, x.w);              \
            qh[i_].z = f2h2(y.x, y.y); qh[i_].w = f2h2(y.z, y.w);              \
            const float* pk = Kb + (size_t)r_ * D_ + (kk) + lc * 8;            \
            x = *reinterpret_cast<const float4*>(pk);                          \
            y = *reinterpret_cast<const float4*>(pk + 4);                      \
            kh[i_].x = f2h2(x.x, x.y); kh[i_].y = f2h2(x.z, x.w);              \
            kh[i_].z = f2h2(y.x, y.y); kh[i_].w = f2h2(y.z, y.w);              \
        }                                                                      \
    } while (0)

    #define QK_STS(st) do {                                                    \
        uint32_t bA_ = smem_u + (uint32_t)(st) * 32768u;                       \
        uint32_t bB_ = bA_ + 16384u;                                           \
        _Pragma("unroll")                                                      \
        for (int i_ = 0; i_ < 4; i_++) {                                       \
            uint32_t off_ = (uint32_t)((lr + i_ * 32) * 128) + psw;            \
            asm volatile("st.shared.v4.b32 [%0], {%1,%2,%3,%4};" ::            \
                "r"(bA_ + off_), "r"(qh[i_].x), "r"(qh[i_].y),                 \
                "r"(qh[i_].z), "r"(qh[i_].w) : "memory");                      \
            asm volatile("st.shared.v4.b32 [%0], {%1,%2,%3,%4};" ::            \
                "r"(bB_ + off_), "r"(kh[i_].x), "r"(kh[i_].y),                 \
                "r"(kh[i_].z), "r"(kh[i_].w) : "memory");                      \
        }                                                                      \
    } while (0)

    // B fragments for one k16: 2 x ldsm4 covering 4 n8-blocks.
    // lanes 0-7: (n_base+l7, k-lo)  8-15: (n_base+l7, k-hi)
    // 16-23: (n_base+8+l7, k-lo)    24-31: (n_base+8+l7, k-hi)
    #define QK_LDB(dst, bB, ks_) do {                                          \
        _Pragma("unroll")                                                      \
        for (int p_ = 0; p_ < 2; p_++) {                                       \
            int n_ = wn * 32 + p_ * 16 + nb8 + l7;                             \
            uint32_t ad_ = (bB) + (uint32_t)(n_ * 128)                         \
                         + (uint32_t)(((((ks_) << 1) + lb1) ^ l7) << 4);       \
            ldsm4(dst[2*p_][0], dst[2*p_][1], dst[2*p_+1][0], dst[2*p_+1][1], ad_); \
        }                                                                      \
    } while (0)

    #define QK_LDA(dst, bA, ks_, im_) do {                                     \
        int r_ = wm * 64 + (im_) * 16 + l7 + lb1 * 8;                          \
        uint32_t ad_ = (bA) + (uint32_t)(r_ * 128)                             \
                     + (uint32_t)(((((ks_) << 1) + lb2) ^ l7) << 4);           \
        ldsm4(dst[0], dst[1], dst[2], dst[3], ad_);                            \
    } while (0)

    QK_LDG(0);
    QK_STS(0);
    QK_LDG(64);
    __syncthreads();

    for (int t = 0; t < 8; t++) {                // D/64 = 8 k-tiles
        const uint32_t bA = smem_u + (uint32_t)(t % 3) * 32768u;
        const uint32_t bB = bA + 16384u;

        uint32_t bfb[2][4][2];
        uint32_t af[2][4];

        // critical-path fragment loads first, then producer traffic
        QK_LDB(bfb[0], bB, 0);
        QK_LDA(af[0], bA, 0, 0);

        if (t + 1 < 8) {
            QK_STS((t + 1) % 3);
            if (t + 2 < 8) QK_LDG((t + 2) * 64);
        }

        #pragma unroll
        for (int u = 0; u < 16; u++) {
            const int ks = u >> 2, im = u & 3;
            if (im == 0 && ks < 3) QK_LDB(bfb[(ks + 1) & 1], bB, ks + 1);
            if (u < 15) QK_LDA(af[(u + 1) & 1], bA, (u + 1) >> 2, (u + 1) & 3);
            #pragma unroll
            for (int in_ = 0; in_ < 4; in_++)
                mma_f16(acc[im][in_], af[u & 1], bfb[ks & 1][in_]);
        }
        __syncthreads();
    }
    #undef QK_LDG
    #undef QK_STS
    #undef QK_LDB
    #undef QK_LDA

    // Epilogue: scale + mask, write masked_vec.
    const int* repb = rep + b * S_;
    #pragma unroll
    for (int im = 0; im < 4; im++) {
        int mA = m0 + wm * 64 + im * 16 + gID;
        int mB = mA + 8;
        int rqA = repb[mA], rqB = repb[mB];
        #pragma unroll
        for (int in_ = 0; in_ < 4; in_++) {
            int n = n0 + wn * 32 + in_ * 8 + tig * 2;
            int rk0 = repb[n], rk1 = repb[n + 1];
            float v00 = acc[im][in_][0] * SCALE;
            float v01 = acc[im][in_][1] * SCALE;
            float v10 = acc[im][in_][2] * SCALE;
            float v11 = acc[im][in_][3] * SCALE;
            attn_b[(size_t)mA * S_ + n]     = (n     < mA && rqA && rk0) ? v00 : 0.f;
            attn_b[(size_t)mA * S_ + n + 1] = (n + 1 < mA && rqA && rk1) ? v01 : 0.f;
            attn_b[(size_t)mB * S_ + n]     = (n     < mB && rqB && rk0) ? v10 : 0.f;
            attn_b[(size_t)mB * S_ + n + 1] = (n + 1 < mB && rqB && rk1) ? v11 : 0.f;
        }
    }
}

// ---------------------------------------------------------------------------
// Kernel 2: in-place row softmax, TRIANGULAR: only k < q is read/written.
// Upper region already holds exact zeros from qk (= its softmax value).
// ---------------------------------------------------------------------------
__global__ __launch_bounds__(256) void softmax_kernel(
    float* attn_param, const int* __restrict__ rep)
{
    float* attn = attn_param ? attn_param : g_attn_scratch;
    const int q = blockIdx.x, b = blockIdx.y;
    if (q == 0) return;                        // row 0: all masked, already 0
    float* row = attn + ((size_t)b * S_ + q) * S_;
    const int tid = threadIdx.x;
    const int k0 = tid * 4;
    const bool active = (k0 < q);

    float4 v = make_float4(0.f, 0.f, 0.f, 0.f);
    int4 rk = make_int4(0, 0, 0, 0);
    if (active) {
        v = reinterpret_cast<float4*>(row)[tid];
        rk = reinterpret_cast<const int4*>(rep + b * S_)[tid];
    }
    const int rq = rep[b * S_ + q];

    __shared__ float red_max[8];
    __shared__ float red_sum[8];

    float mx = fmaxf(fmaxf(fmaxf(v.x, v.y), fmaxf(v.z, v.w)), 0.f);
    #pragma unroll
    for (int o = 16; o; o >>= 1) mx = fmaxf(mx, __shfl_xor_sync(0xffffffffu, mx, o));
    if ((tid & 31) == 0) red_max[tid >> 5] = mx;
    __syncthreads();
    mx = red_max[0];
    #pragma unroll
    for (int w = 1; w < 8; w++) mx = fmaxf(mx, red_max[w]);

    const bool m0b = (k0     < q) && rq && rk.x;
    const bool m1b = (k0 + 1 < q) && rq && rk.y;
    const bool m2b = (k0 + 2 < q) && rq && rk.z;
    const bool m3b = (k0 + 3 < q) && rq && rk.w;
    float e0 = m0b ? __expf(v.x - mx) : 0.f;
    float e1 = m1b ? __expf(v.y - mx) : 0.f;
    float e2 = m2b ? __expf(v.z - mx) : 0.f;
    float e3 = m3b ? __expf(v.w - mx) : 0.f;

    float sden = (e0 + e1) + (e2 + e3);
    #pragma unroll
    for (int o = 16; o; o >>= 1) sden += __shfl_xor_sync(0xffffffffu, sden, o);
    if ((tid & 31) == 0) red_sum[tid >> 5] = sden;
    __syncthreads();
    sden = red_sum[0];
    #pragma unroll
    for (int w = 1; w < 8; w++) sden += red_sum[w];

    float s2 = sden + ((sden == 0.f) ? 1.f : 0.f);
    float inv = 1.f / (s2 + 1e-20f);

    if (active) {
        v.x = e0 * inv; v.y = e1 * inv; v.z = e2 * inv; v.w = e3 * inv;
        reinterpret_cast<float4*>(row)[tid] = v;
    }
}

// ---------------------------------------------------------------------------
// Kernel 3: out = attn_sm @ V.  fp16 m16n8k16, BK=64, triangular K-loop.
// A (attn) K-major like Q; V is [k][n] n-contiguous -> trans ldmatrix.x4.
// Same fragment pipelining as qk.
// ---------------------------------------------------------------------------
__global__ __launch_bounds__(256, 2) void pv_kernel(
    const float* attn_param, const float* __restrict__ V, float* __restrict__ out)
{
    const float* attn = attn_param ? attn_param : g_attn_scratch;
    const int bm = blockIdx.y, bn = blockIdx.x, b = blockIdx.z;
    const int m0 = bm * 128, n0 = bn * 128;
    const int tid = threadIdx.x;

    extern __shared__ float smem[];              // 3 stages x 32KB (A16K + V16K)
    const uint32_t smem_u = (uint32_t)__cvta_generic_to_shared(smem);

    const int warp = tid >> 5, lane = tid & 31;
    const int wm = warp & 1, wn = warp >> 1;
    const int gID = lane >> 2, tig = lane & 3;

    const float* Ab = attn + ((size_t)b * S_ + m0) * S_;
    const float* Vb = V + (size_t)b * S_ * D_;

    // A producer: rows lr+32i, chunk lc
    const int lr = tid >> 3, lc = tid & 7;
    const uint32_t psw = (uint32_t)((lc ^ (lr & 7)) << 4);
    // V producer: rows vr+16i (k), 16 chunks of 16B per 256B row
    const int vr = tid >> 4, vc = tid & 15;
    const uint32_t vsw = (uint32_t)((vc ^ (vr & 7)) << 4);

    const int l7 = lane & 7;
    const int lb1 = (lane >> 3) & 1;
    const int lb2 = lane >> 4;
    const int nb1 = lb2;                         // n-chunk select for ldsm4t

    float acc[4][4][4];
    #pragma unroll
    for (int i = 0; i < 4; i++)
        #pragma unroll
        for (int j = 0; j < 4; j++)
            #pragma unroll
            for (int r = 0; r < 4; r++) acc[i][j][r] = 0.f;

    const int NT = (bm + 1) * 2;     // k-tiles of 64 f32, strictly-lower bound

    uint4 ah[4], vh[4];

    #define PV_LDG(kk) do {                                                    \
        _Pragma("unroll")                                                      \
        for (int i_ = 0; i_ < 4; i_++) {                                       \
            int r_ = lr + i_ * 32;                                             \
            const float* pa = Ab + (size_t)r_ * S_ + (kk) + lc * 8;            \
            float4 x = *reinterpret_cast<const float4*>(pa);                   \
            float4 y = *reinterpret_cast<const float4*>(pa + 4);               \
            ah[i_].x = f2h2(x.x, x.y); ah[i_].y = f2h2(x.z, x.w);              \
            ah[i_].z = f2h2(y.x, y.y); ah[i_].w = f2h2(y.z, y.w);              \
            int kr_ = vr + i_ * 16;                                            \
            const float* pv = Vb + (size_t)((kk) + kr_) * D_ + n0 + vc * 8;    \
            x = *reinterpret_cast<const float4*>(pv);                          \
            y = *reinterpret_cast<const float4*>(pv + 4);                      \
            vh[i_].x = f2h2(x.x, x.y); vh[i_].y = f2h2(x.z, x.w);              \
            vh[i_].z = f2h2(y.x, y.y); vh[i_].w = f2h2(y.z, y.w);              \
        }                                                                      \
    } while (0)

    #define PV_STS(st) do {                                                    \
        uint32_t bA_ = smem_u + (uint32_t)(st) * 32768u;                       \
        uint32_t bV_ = bA_ + 16384u;                                           \
        _Pragma("unroll")                                                      \
        for (int i_ = 0; i_ < 4; i_++) {                                       \
            uint32_t offA_ = (uint32_t)((lr + i_ * 32) * 128) + psw;           \
            asm volatile("st.shared.v4.b32 [%0], {%1,%2,%3,%4};" ::            \
                "r"(bA_ + offA_), "r"(ah[i_].x), "r"(ah[i_].y),                \
                "r"(ah[i_].z), "r"(ah[i_].w) : "memory");                      \
            uint32_t offV_ = (uint32_t)((vr + i_ * 16) * 256) + vsw;           \
            asm volatile("st.shared.v4.b32 [%0], {%1,%2,%3,%4};" ::            \
                "r"(bV_ + offV_), "r"(vh[i_].x), "r"(vh[i_].y),                \
                "r"(vh[i_].z), "r"(vh[i_].w) : "memory");                      \
        }                                                                      \
    } while (0)

    // V fragments for one k16: 2 x ldsm4.trans covering 4 n8-blocks.
    // lanes 0-7:(k-lo,nch0) 8-15:(k-hi,nch0) 16-23:(k-lo,nch1) 24-31:(k-hi,nch1)
    #define PV_LDB(dst, bV, ks_) do {                                          \
        _Pragma("unroll")                                                      \
        for (int p_ = 0; p_ < 2; p_++) {                                       \
            int kr_ = (ks_) * 16 + l7 + lb1 * 8;                               \
            int nch_ = wn * 4 + 2 * p_ + nb1;                                  \
            uint32_t ad_ = (bV) + (uint32_t)(kr_ * 256)                        \
                         + (uint32_t)((nch_ ^ l7) << 4);                       \
            ldsm4t(dst[2*p_][0], dst[2*p_][1], dst[2*p_+1][0], dst[2*p_+1][1], ad_); \
        }                                                                      \
    } while (0)

    #define PV_LDA(dst, bA, ks_, im_) do {                                     \
        int r_ = wm * 64 + (im_) * 16 + l7 + lb1 * 8;                          \
        uint32_t ad_ = (bA) + (uint32_t)(r_ * 128)                             \
                     + (uint32_t)(((((ks_) << 1) + lb2) ^ l7) << 4);           \
        ldsm4(dst[0], dst[1], dst[2], dst[3], ad_);                            \
    } while (0)

    PV_LDG(0);
    PV_STS(0);
    PV_LDG(64);                      // NT >= 2 always
    __syncthreads();

    for (int t = 0; t < NT; t++) {
        const uint32_t bA = smem_u + (uint32_t)(t % 3) * 32768u;
        const uint32_t bV = bA + 16384u;

        uint32_t bfb[2][4][2];
        uint32_t af[2][4];

        PV_LDB(bfb[0], bV, 0);
        PV_LDA(af[0], bA, 0, 0);

        if (t + 1 < NT) {
            PV_STS((t + 1) % 3);
            if (t + 2 < NT) PV_LDG((t + 2) * 64);
        }

        #pragma unroll
        for (int u = 0; u < 16; u++) {
            const int ks = u >> 2, im = u & 3;
            if (im == 0 && ks < 3) PV_LDB(bfb[(ks + 1) & 1], bV, ks + 1);
            if (u < 15) PV_LDA(af[(u + 1) & 1], bA, (u + 1) >> 2, (u + 1) & 3);
            #pragma unroll
            for (int in_ = 0; in_ < 4; in_++)
                mma_f16(acc[im][in_], af[u & 1], bfb[ks & 1][in_]);
        }
        __syncthreads();
    }
    #undef PV_LDG
    #undef PV_STS
    #undef PV_LDB
    #undef PV_LDA

    #pragma unroll
    for (int im = 0; im < 4; im++) {
        int mA = m0 + wm * 64 + im * 16 + gID;
        int mB = mA + 8;
        #pragma unroll
        for (int in_ = 0; in_ < 4; in_++) {
            int n = n0 + wn * 32 + in_ * 8 + tig * 2;
            out[((size_t)b * S_ + mA) * D_ + n]     = acc[im][in_][0];
            out[((size_t)b * S_ + mA) * D_ + n + 1] = acc[im][in_][1];
            out[((size_t)b * S_ + mB) * D_ + n]     = acc[im][in_][2];
            out[((size_t)b * S_ + mB) * D_ + n + 1] = acc[im][in_][3];
        }
    }
}

extern "C" void kernel_launch(void* const* d_in, const int* in_sizes, int n_in,
                              void* d_out, int out_size)
{
    const float* q   = (const float*)d_in[0];
    const float* k   = (const float*)d_in[1];
    const float* v   = (const float*)d_in[2];
    const int*   rep = (const int*)d_in[3];
    float* out = (float*)d_out;

    const long OUT_ELEMS  = (long)B_ * S_ * D_;   // 16,777,216
    const long ATTN_ELEMS = (long)B_ * S_ * S_;   // 33,554,432

    float* attn = nullptr;  // nullptr -> kernels fall back to g_attn_scratch
    if ((long)out_size >= OUT_ELEMS + ATTN_ELEMS)
        attn = out + OUT_ELEMS;

    const int SMEM3 = 3 * 32768;   // 98304 B for both GEMM kernels
    cudaFuncSetAttribute(qk_kernel, cudaFuncAttributeMaxDynamicSharedMemorySize, SMEM3);
    cudaFuncSetAttribute(pv_kernel, cudaFuncAttributeMaxDynamicSharedMemorySize, SMEM3);

    dim3 g1(8, 8, B_);
    qk_kernel<<<g1, 256, SMEM3>>>(q, k, rep, attn);

    dim3 g2(S_, B_);
    softmax_kernel<<<g2, 256>>>(attn, rep);

    dim3 g3(4, 8, B_);
    pv_kernel<<<g3, 256, SMEM3>>>(attn, v, out);
}

// round 16
// speedup vs baseline: 1.1131x; 1.1131x over previous
#include <cuda_runtime.h>
#include <cuda_fp16.h>
#include <cstdint>

#define B_ 32
#define S_ 1024
#define D_ 512
#define SCALE 0.044194173824159216f   // 1/sqrt(512)

// Fallback scratch in case out_size does not include the attn_sm output.
__device__ float g_attn_scratch[(size_t)B_ * S_ * S_];

// pack two f32 -> f16x2 (lo = first element), round-to-nearest
__device__ __forceinline__ uint32_t f2h2(float lo, float hi) {
    uint32_t r;
    asm("cvt.rn.f16x2.f32 %0, %1, %2;" : "=r"(r) : "f"(hi), "f"(lo));
    return r;
}

__device__ __forceinline__ void mma_f16(float* c, const uint32_t* a, const uint32_t* b) {
    asm volatile(
        "mma.sync.aligned.m16n8k16.row.col.f32.f16.f16.f32 "
        "{%0,%1,%2,%3}, {%4,%5,%6,%7}, {%8,%9}, {%0,%1,%2,%3};\n"
        : "+f"(c[0]), "+f"(c[1]), "+f"(c[2]), "+f"(c[3])
        : "r"(a[0]), "r"(a[1]), "r"(a[2]), "r"(a[3]),
          "r"(b[0]), "r"(b[1]));
}
__device__ __forceinline__ void ldsm4(uint32_t& r0, uint32_t& r1, uint32_t& r2, uint32_t& r3, uint32_t a) {
    asm volatile("ldmatrix.sync.aligned.m8n8.x4.shared.b16 {%0,%1,%2,%3}, [%4];"
                 : "=r"(r0), "=r"(r1), "=r"(r2), "=r"(r3) : "r"(a));
}
__device__ __forceinline__ void ldsm2(uint32_t& r0, uint32_t& r1, uint32_t a) {
    asm volatile("ldmatrix.sync.aligned.m8n8.x2.shared.b16 {%0,%1}, [%2];"
                 : "=r"(r0), "=r"(r1) : "r"(a));
}
__device__ __forceinline__ void ldsm2t(uint32_t& r0, uint32_t& r1, uint32_t a) {
    asm volatile("ldmatrix.sync.aligned.m8n8.x2.trans.shared.b16 {%0,%1}, [%2];"
                 : "=r"(r0), "=r"(r1) : "r"(a));
}

// ---------------------------------------------------------------------------
// Kernel 1: masked_vec = (Q K^T)*SCALE*mask.  128x128 tile, BK=64 (f32 cols),
// fp16 m16n8k16 MMA, 3-stage smem ring, producer LDG f32 -> cvt f16x2 -> STS.
// (R13 structure — best measured variant.)
// ---------------------------------------------------------------------------
__global__ __launch_bounds__(256, 2) void qk_kernel(
    const float* __restrict__ Q, const float* __restrict__ K,
    const int* __restrict__ rep, float* __restrict__ attn_param)
{
    float* attn = attn_param ? attn_param : g_attn_scratch;
    const int bm = blockIdx.y, bn = blockIdx.x, b = blockIdx.z;
    const int m0 = bm * 128, n0 = bn * 128;
    const int tid = threadIdx.x;
    float* attn_b = attn + (size_t)b * S_ * S_;

    if (bn > bm) {
        float4 z = make_float4(0.f, 0.f, 0.f, 0.f);
        #pragma unroll
        for (int i = 0; i < 16; i++) {
            int idx = tid + i * 256;
            int r = idx >> 5, c = idx & 31;
            reinterpret_cast<float4*>(attn_b + (size_t)(m0 + r) * S_ + n0)[c] = z;
        }
        return;
    }

    extern __shared__ float smem[];              // 3 stages x 32KB (A16K + B16K)
    const uint32_t smem_u = (uint32_t)__cvta_generic_to_shared(smem);

    const int warp = tid >> 5, lane = tid & 31;
    const int wm = warp & 1, wn = warp >> 1;
    const int gID = lane >> 2, tig = lane & 3;

    const float* Qb = Q + ((size_t)b * S_ + m0) * D_;
    const float* Kb = K + ((size_t)b * S_ + n0) * D_;

    // producer: 8 threads per row (32B f32 each), rows lr+32i, chunk = lc
    const int lr = tid >> 3, lc = tid & 7;
    const uint32_t psw = (uint32_t)((lc ^ (lr & 7)) << 4);

    const int l7 = lane & 7;
    const int lb1 = (lane >> 3) & 1;
    const int lb2 = lane >> 4;

    float acc[4][4][4];
    #pragma unroll
    for (int i = 0; i < 4; i++)
        #pragma unroll
        for (int j = 0; j < 4; j++)
            #pragma unroll
            for (int r = 0; r < 4; r++) acc[i][j][r] = 0.f;

    uint4 qh[4], kh[4];

    #define QK_LDG(kk) do {                                                    \
        _Pragma("unroll")                                                      \
        for (int i_ = 0; i_ < 4; i_++) {                                       \
            int r_ = lr + i_ * 32;                                             \
            const float* pq = Qb + (size_t)r_ * D_ + (kk) + lc * 8;            \
            float4 x = *reinterpret_cast<const float4*>(pq);                   \
            float4 y = *reinterpret_cast<const float4*>(pq + 4);               \
            qh[i_].x = f2h2(x.x, x.y); qh[i_].y = f2h2(x.z, x.w);              \
            qh[i_].z = f2h2(y.x, y.y); qh[i_].w = f2h2(y.z, y.w);              \
            const float* pk = Kb + (size_t)r_ * D_ + (kk) + lc * 8;            \
            x = *reinterpret_cast<const float4*>(pk);                          \
            y = *reinterpret_cast<const float4*>(pk + 4);                      \
            kh[i_].x = f2h2(x.x, x.y); kh[i_].y = f2h2(x.z, x.w);              \
            kh[i_].z = f2h2(y.x, y.y); kh[i_].w = f2h2(y.z, y.w);              \
        }                                                                      \
    } while (0)

    #define QK_STS(st) do {                                                    \
        uint32_t bA_ = smem_u + (uint32_t)(st) * 32768u;                       \
        uint32_t bB_ = bA_ + 16384u;                                           \
        _Pragma("unroll")                                                      \
        for (int i_ = 0; i_ < 4; i_++) {                                       \
            uint32_t off_ = (uint32_t)((lr + i_ * 32) * 128) + psw;            \
            asm volatile("st.shared.v4.b32 [%0], {%1,%2,%3,%4};" ::            \
                "r"(bA_ + off_), "r"(qh[i_].x), "r"(qh[i_].y),                 \
                "r"(qh[i_].z), "r"(qh[i_].w) : "memory");                      \
            asm volatile("st.shared.v4.b32 [%0], {%1,%2,%3,%4};" ::            \
                "r"(bB_ + off_), "r"(kh[i_].x), "r"(kh[i_].y),                 \
                "r"(kh[i_].z), "r"(kh[i_].w) : "memory");                      \
        }                                                                      \
    } while (0)

    QK_LDG(0);
    QK_STS(0);
    QK_LDG(64);
    __syncthreads();

    for (int t = 0; t < 8; t++) {                // D/64 = 8 k-tiles
        const uint32_t bA = smem_u + (uint32_t)(t % 3) * 32768u;
        const uint32_t bB = bA + 16384u;

        if (t + 1 < 8) {
            QK_STS((t + 1) % 3);
            if (t + 2 < 8) QK_LDG((t + 2) * 64);
        }

        #pragma unroll
        for (int ks = 0; ks < 4; ks++) {         // 4 x k16 per tile
            uint32_t bf[4][2];
            #pragma unroll
            for (int in_ = 0; in_ < 4; in_++) {
                int n = wn * 32 + in_ * 8 + l7;
                uint32_t addr = bB + (uint32_t)(n * 128)
                              + (uint32_t)((((ks << 1) + lb1) ^ l7) << 4);
                ldsm2(bf[in_][0], bf[in_][1], addr);
            }
            #pragma unroll
            for (int im = 0; im < 4; im++) {
                int r = wm * 64 + im * 16 + l7 + lb1 * 8;
                uint32_t addr = bA + (uint32_t)(r * 128)
                              + (uint32_t)((((ks << 1) + lb2) ^ l7) << 4);
                uint32_t a[4];
                ldsm4(a[0], a[1], a[2], a[3], addr);
                #pragma unroll
                for (int in_ = 0; in_ < 4; in_++)
                    mma_f16(acc[im][in_], a, bf[in_]);
            }
        }
        __syncthreads();
    }
    #undef QK_LDG
    #undef QK_STS

    // Epilogue: scale + mask, write masked_vec.
    const int* repb = rep + b * S_;
    #pragma unroll
    for (int im = 0; im < 4; im++) {
        int mA = m0 + wm * 64 + im * 16 + gID;
        int mB = mA + 8;
        int rqA = repb[mA], rqB = repb[mB];
        #pragma unroll
        for (int in_ = 0; in_ < 4; in_++) {
            int n = n0 + wn * 32 + in_ * 8 + tig * 2;
            int rk0 = repb[n], rk1 = repb[n + 1];
            float v00 = acc[im][in_][0] * SCALE;
            float v01 = acc[im][in_][1] * SCALE;
            float v10 = acc[im][in_][2] * SCALE;
            float v11 = acc[im][in_][3] * SCALE;
            attn_b[(size_t)mA * S_ + n]     = (n     < mA && rqA && rk0) ? v00 : 0.f;
            attn_b[(size_t)mA * S_ + n + 1] = (n + 1 < mA && rqA && rk1) ? v01 : 0.f;
            attn_b[(size_t)mB * S_ + n]     = (n     < mB && rqB && rk0) ? v10 : 0.f;
            attn_b[(size_t)mB * S_ + n + 1] = (n + 1 < mB && rqB && rk1) ? v11 : 0.f;
        }
    }
}

// ---------------------------------------------------------------------------
// Kernel 2: warp-per-row softmax, triangular (only k < q touched).
// 8 rows per block; rep row cached in smem once; reductions are pure
// shuffles (no __syncthreads in the hot path); row kept in registers.
// ---------------------------------------------------------------------------
__global__ __launch_bounds__(256) void softmax_kernel(
    float* attn_param, const int* __restrict__ rep)
{
    float* attn = attn_param ? attn_param : g_attn_scratch;
    const int b = blockIdx.y;
    const int warp = threadIdx.x >> 5, lane = threadIdx.x & 31;
    const int q = blockIdx.x * 8 + warp;

    __shared__ int rk_s[S_];
    #pragma unroll
    for (int i = 0; i < 1; i++) {  // 1024 ints = 256 int4, one per thread
        reinterpret_cast<int4*>(rk_s)[threadIdx.x] =
            reinterpret_cast<const int4*>(rep + (size_t)b * S_)[threadIdx.x];
    }
    __syncthreads();

    if (q == 0) return;                  // row 0 fully masked, already zeros

    float* row = attn + ((size_t)b * S_ + q) * S_;
    const int rq = rk_s[q];
    const int nch = (q + 127) >> 7;      // 128-float chunks covering k < q

    float4 v[8];
    float mx = 0.f;                      // structural zeros are in every row
    #pragma unroll
    for (int c = 0; c < 8; c++) {
        if (c < nch) {
            v[c] = reinterpret_cast<float4*>(row)[c * 32 + lane];
            mx = fmaxf(mx, fmaxf(fmaxf(v[c].x, v[c].y), fmaxf(v[c].z, v[c].w)));
        }
    }
    #pragma unroll
    for (int o = 16; o; o >>= 1) mx = fmaxf(mx, __shfl_xor_sync(0xffffffffu, mx, o));

    float sum = 0.f;
    #pragma unroll
    for (int c = 0; c < 8; c++) {
        if (c < nch) {
            const int k0 = c * 128 + lane * 4;
            float e0 = (k0     < q && rq && rk_s[k0])     ? __expf(v[c].x - mx) : 0.f;
            float e1 = (k0 + 1 < q && rq && rk_s[k0 + 1]) ? __expf(v[c].y - mx) : 0.f;
            float e2 = (k0 + 2 < q && rq && rk_s[k0 + 2]) ? __expf(v[c].z - mx) : 0.f;
            float e3 = (k0 + 3 < q && rq && rk_s[k0 + 3]) ? __expf(v[c].w - mx) : 0.f;
            v[c].x = e0; v[c].y = e1; v[c].z = e2; v[c].w = e3;
            sum += (e0 + e1) + (e2 + e3);
        }
    }
    #pragma unroll
    for (int o = 16; o; o >>= 1) sum += __shfl_xor_sync(0xffffffffu, sum, o);

    float s2 = sum + ((sum == 0.f) ? 1.f : 0.f);
    float inv = 1.f / (s2 + 1e-20f);

    #pragma unroll
    for (int c = 0; c < 8; c++) {
        if (c < nch) {
            v[c].x *= inv; v[c].y *= inv; v[c].z *= inv; v[c].w *= inv;
            reinterpret_cast<float4*>(row)[c * 32 + lane] = v[c];
        }
    }
}

// ---------------------------------------------------------------------------
// Kernel 3: out = attn_sm @ V.  fp16 m16n8k16, BK=64, triangular K-loop.
// (R13 structure — best measured variant.)
// ---------------------------------------------------------------------------
__global__ __launch_bounds__(256, 2) void pv_kernel(
    const float* attn_param, const float* __restrict__ V, float* __restrict__ out)
{
    const float* attn = attn_param ? attn_param : g_attn_scratch;
    const int bm = blockIdx.y, bn = blockIdx.x, b = blockIdx.z;
    const int m0 = bm * 128, n0 = bn * 128;
    const int tid = threadIdx.x;

    extern __shared__ float smem[];              // 3 stages x 32KB (A16K + V16K)
    const uint32_t smem_u = (uint32_t)__cvta_generic_to_shared(smem);

    const int warp = tid >> 5, lane = tid & 31;
    const int wm = warp & 1, wn = warp >> 1;
    const int gID = lane >> 2, tig = lane & 3;

    const float* Ab = attn + ((size_t)b * S_ + m0) * S_;
    const float* Vb = V + (size_t)b * S_ * D_;

    const int lr = tid >> 3, lc = tid & 7;
    const uint32_t psw = (uint32_t)((lc ^ (lr & 7)) << 4);
    const int vr = tid >> 4, vc = tid & 15;
    const uint32_t vsw = (uint32_t)((vc ^ (vr & 7)) << 4);

    const int l7 = lane & 7;
    const int lb1 = (lane >> 3) & 1;
    const int lb2 = lane >> 4;

    float acc[4][4][4];
    #pragma unroll
    for (int i = 0; i < 4; i++)
        #pragma unroll
        for (int j = 0; j < 4; j++)
            #pragma unroll
            for (int r = 0; r < 4; r++) acc[i][j][r] = 0.f;

    const int NT = (bm + 1) * 2;     // k-tiles of 64 f32, strictly-lower bound

    uint4 ah[4], vh[4];

    #define PV_LDG(kk) do {                                                    \
        _Pragma("unroll")                                                      \
        for (int i_ = 0; i_ < 4; i_++) {                                       \
            int r_ = lr + i_ * 32;                                             \
            const float* pa = Ab + (size_t)r_ * S_ + (kk) + lc * 8;            \
            float4 x = *reinterpret_cast<const float4*>(pa);                   \
            float4 y = *reinterpret_cast<const float4*>(pa + 4);               \
            ah[i_].x = f2h2(x.x, x.y); ah[i_].y = f2h2(x.z, x.w);              \
            ah[i_].z = f2h2(y.x, y.y); ah[i_].w = f2h2(y.z, y.w);              \
            int kr_ = vr + i_ * 16;                                            \
            const float* pv = Vb + (size_t)((kk) + kr_) * D_ + n0 + vc * 8;    \
            x = *reinterpret_cast<const float4*>(pv);                          \
            y = *reinterpret_cast<const float4*>(pv + 4);                      \
            vh[i_].x = f2h2(x.x, x.y); vh[i_].y = f2h2(x.z, x.w);              \
            vh[i_].z = f2h2(y.x, y.y); vh[i_].w = f2h2(y.z, y.w);              \
        }                                                                      \
    } while (0)

    #define PV_STS(st) do {                                                    \
        uint32_t bA_ = smem_u + (uint32_t)(st) * 32768u;                       \
        uint32_t bV_ = bA_ + 16384u;                                           \
        _Pragma("unroll")                                                      \
        for (int i_ = 0; i_ < 4; i_++) {                                       \
            uint32_t offA_ = (uint32_t)((lr + i_ * 32) * 128) + psw;           \
            asm volatile("st.shared.v4.b32 [%0], {%1,%2,%3,%4};" ::            \
                "r"(bA_ + offA_), "r"(ah[i_].x), "r"(ah[i_].y),                \
                "r"(ah[i_].z), "r"(ah[i_].w) : "memory");                      \
            uint32_t offV_ = (uint32_t)((vr + i_ * 16) * 256) + vsw;           \
            asm volatile("st.shared.v4.b32 [%0], {%1,%2,%3,%4};" ::            \
                "r"(bV_ + offV_), "r"(vh[i_].x), "r"(vh[i_].y),                \
                "r"(vh[i_].z), "r"(vh[i_].w) : "memory");                      \
        }                                                                      \
    } while (0)

    PV_LDG(0);
    PV_STS(0);
    PV_LDG(64);                      // NT >= 2 always
    __syncthreads();

    for (int t = 0; t < NT; t++) {
        const uint32_t bA = smem_u + (uint32_t)(t % 3) * 32768u;
        const uint32_t bV = bA + 16384u;

        if (t + 1 < NT) {
            PV_STS((t + 1) % 3);
            if (t + 2 < NT) PV_LDG((t + 2) * 64);
        }

        #pragma unroll
        for (int ks = 0; ks < 4; ks++) {
            uint32_t bf[4][2];
            #pragma unroll
            for (int in_ = 0; in_ < 4; in_++) {
                int nch = wn * 4 + in_;
                int kr = ks * 16 + l7 + lb1 * 8;
                uint32_t addr = bV + (uint32_t)(kr * 256)
                              + (uint32_t)((nch ^ l7) << 4);
                ldsm2t(bf[in_][0], bf[in_][1], addr);
            }
            #pragma unroll
            for (int im = 0; im < 4; im++) {
                int r = wm * 64 + im * 16 + l7 + lb1 * 8;
                uint32_t addr = bA + (uint32_t)(r * 128)
                              + (uint32_t)((((ks << 1) + lb2) ^ l7) << 4);
                uint32_t a[4];
                ldsm4(a[0], a[1], a[2], a[3], addr);
                #pragma unroll
                for (int in_ = 0; in_ < 4; in_++)
                    mma_f16(acc[im][in_], a, bf[in_]);
            }
        }
        __syncthreads();
    }
    #undef PV_LDG
    #undef PV_STS

    #pragma unroll
    for (int im = 0; im < 4; im++) {
        int mA = m0 + wm * 64 + im * 16 + gID;
        int mB = mA + 8;
        #pragma unroll
        for (int in_ = 0; in_ < 4; in_++) {
            int n = n0 + wn * 32 + in_ * 8 + tig * 2;
            out[((size_t)b * S_ + mA) * D_ + n]     = acc[im][in_][0];
            out[((size_t)b * S_ + mA) * D_ + n + 1] = acc[im][in_][1];
            out[((size_t)b * S_ + mB) * D_ + n]     = acc[im][in_][2];
            out[((size_t)b * S_ + mB) * D_ + n + 1] = acc[im][in_][3];
        }
    }
}

extern "C" void kernel_launch(void* const* d_in, const int* in_sizes, int n_in,
                              void* d_out, int out_size)
{
    const float* q   = (const float*)d_in[0];
    const float* k   = (const float*)d_in[1];
    const float* v   = (const float*)d_in[2];
    const int*   rep = (const int*)d_in[3];
    float* out = (float*)d_out;

    const long OUT_ELEMS  = (long)B_ * S_ * D_;   // 16,777,216
    const long ATTN_ELEMS = (long)B_ * S_ * S_;   // 33,554,432

    float* attn = nullptr;  // nullptr -> kernels fall back to g_attn_scratch
    if ((long)out_size >= OUT_ELEMS + ATTN_ELEMS)
        attn = out + OUT_ELEMS;

    const int SMEM3 = 3 * 32768;   // 98304 B for both GEMM kernels
    cudaFuncSetAttribute(qk_kernel, cudaFuncAttributeMaxDynamicSharedMemorySize, SMEM3);
    cudaFuncSetAttribute(pv_kernel, cudaFuncAttributeMaxDynamicSharedMemorySize, SMEM3);

    dim3 g1(8, 8, B_);
    qk_kernel<<<g1, 256, SMEM3>>>(q, k, rep, attn);

    dim3 g2(S_ / 8, B_);           // warp-per-row: 8 rows per 256-thread block
    softmax_kernel<<<g2, 256>>>(attn, rep);

    dim3 g3(4, 8, B_);
    pv_kernel<<<g3, 256, SMEM3>>>(attn, v, out);
}